// round 17
// baseline (speedup 1.0000x reference)
#include <cuda_runtime.h>
#include <cuda_fp16.h>
#include <cstdint>

// Problem constants
#define H     80
#define B     4096
#define T     512
#define NROW  32
#define NCTA  128
#define NTHR  640           // 20 warps; warp w owns gr-range [16w, 16w+16) (2 n-tiles)

#define KA1   88            // weight stage stride (halves); odd/16 -> conflict-free
#define KB    168           // h buffer stride (halves); odd/16
#define GS    324           // gates f32 stride ([r][gr] transposed)

#define WBLK_BYTES (320 * KA1 * 2)   // 56320 per weight block
#define B_BYTES    (NROW * KB * 2)   // 10752
#define G_BYTES    (NROW * GS * 4)   // 41472

// smem offsets (bytes) -- weights are NOT resident (staged transiently in G1/G2)
#define SM_B    0
#define SM_G1   (SM_B + B_BYTES)             // 10752 ; also weight staging at init
#define SM_G2   (SM_G1 + G_BYTES)            // 52224
#define SM_BIAS (SM_G2 + G_BYTES)            // 93696
#define SM_W1X  (SM_BIAS + 2560)             // 96256
#define SM_WLIN (SM_W1X + 1280)              // 97536
#define SM_X    (SM_WLIN + 320)              // 97856 (2 x 32 f32)
#define SM_PART (SM_X + 256)                 // 98112 (128 f32)
#define SMEM_TOTAL (SM_PART + 512 + 64)      // ~98.7 KB
#define SM_STAGE SM_G1                        // 83 KB window >= 56 KB block

// packed weights: 3 blocks [320][KA1]: 0=w_hh1, 1=w_ih2, 2=w_hh2 (gr = 4j+g)
__device__ __align__(16) __half g_Wh[3 * 320 * KA1];

static __device__ __forceinline__ uint32_t smem_u32(const void *p) {
    uint32_t a;
    asm("{ .reg .u64 t; cvta.to.shared.u64 t, %1; cvt.u32.u64 %0, t; }" : "=r"(a) : "l"(p));
    return a;
}
static __device__ __forceinline__ float tanhap(float x) {
    float y; asm("tanh.approx.f32 %0, %1;" : "=f"(y) : "f"(x)); return y;
}
static __device__ __forceinline__ float sigf(float x) {
    return fmaf(0.5f, tanhap(0.5f * x), 0.5f);
}

#define LDSM_X4(r0, r1, r2, r3, addr) \
    asm volatile("ldmatrix.sync.aligned.m8n8.x4.shared.b16 {%0,%1,%2,%3}, [%4];" \
                 : "=r"(r0), "=r"(r1), "=r"(r2), "=r"(r3) : "r"(addr))
#define MMA16816(d, a0, a1, a2, a3, b0, b1) \
    asm volatile("mma.sync.aligned.m16n8k16.row.col.f32.f16.f16.f32 " \
                 "{%0,%1,%2,%3}, {%4,%5,%6,%7}, {%8,%9}, {%0,%1,%2,%3};" \
                 : "+f"((d)[0]), "+f"((d)[1]), "+f"((d)[2]), "+f"((d)[3]) \
                 : "r"(a0), "r"(a1), "r"(a2), "r"(a3), "r"(b0), "r"(b1))

// ---------------------------------------------------------------------------
__global__ void pack_w_kernel(const float *__restrict__ whh1,
                              const float *__restrict__ wih2,
                              const float *__restrict__ whh2) {
    int idx = blockIdx.x * blockDim.x + threadIdx.x;
    if (idx >= 3 * 320 * KA1) return;
    int blk = idx / (320 * KA1), rem = idx % (320 * KA1);
    int gr = rem / KA1, k = rem % KA1;
    int g = gr & 3, j = gr >> 2;
    int row = g * 80 + j;
    float v = 0.0f;
    if (k < 80) {
        const float *src = (blk == 0) ? whh1 : (blk == 1) ? wih2 : whh2;
        v = src[row * 80 + k];
    }
    g_Wh[idx] = __float2half_rn(v);
}

// hoist one weight block's B-fragments (this warp's 2 n-tiles, 5 chunks)
static __device__ __forceinline__ void hoistW(uint32_t (&bW)[5][2][2], uint32_t stBase) {
#pragma unroll
    for (int c = 0; c < 5; c++)
        LDSM_X4(bW[c][0][0], bW[c][0][1], bW[c][1][0], bW[c][1][1], stBase + c * 32);
}

// gemm: 5 chunks; A = h (2 m-tiles = 32 rows) via LDSM at aB (+KOFF bytes for h2);
// B = register-resident weight frags. Accumulates into d[mt][nt][4].
static __device__ __forceinline__ void gemmS(const uint32_t (&bW)[5][2][2],
                                             uint32_t aB, float (&d)[2][2][4]) {
#pragma unroll
    for (int c = 0; c < 5; c++) {
        uint32_t a[2][4];
#pragma unroll
        for (int mt = 0; mt < 2; mt++)
            LDSM_X4(a[mt][0], a[mt][1], a[mt][2], a[mt][3],
                    aB + mt * (16 * KB * 2) + c * 32);
#pragma unroll
        for (int mt = 0; mt < 2; mt++)
#pragma unroll
            for (int nt = 0; nt < 2; nt++)
                MMA16816(d[mt][nt], a[mt][0], a[mt][1], a[mt][2], a[mt][3],
                         bW[c][nt][0], bW[c][nt][1]);
    }
}

static __device__ __forceinline__ void dzero(float (&d)[2][2][4]) {
#pragma unroll
    for (int m = 0; m < 2; m++)
#pragma unroll
        for (int n = 0; n < 2; n++)
#pragma unroll
            for (int q = 0; q < 4; q++) d[m][n][q] = 0.0f;
}

// epilogue: D (m=rows, n=gr) -> gates smem [r][gr]; consecutive gr pairs -> st.v2
static __device__ __forceinline__ void epi(float *gf, const float (&d)[2][2][4],
                                           int wid, int lid) {
    const int gr0 = wid * 16 + 2 * (lid & 3);
    const int r0  = lid >> 2;
#pragma unroll
    for (int mt = 0; mt < 2; mt++)
#pragma unroll
        for (int nt = 0; nt < 2; nt++) {
            const int gr = gr0 + nt * 8;
            const int r  = mt * 16 + r0;
            *(float2 *)(gf + r * GS + gr)       = make_float2(d[mt][nt][0], d[mt][nt][1]);
            *(float2 *)(gf + (r + 8) * GS + gr) = make_float2(d[mt][nt][2], d[mt][nt][3]);
        }
}

// cell: 640 threads; thread (j=tid%80, grp=tid/80) does 4 rows grp*4..+3
static __device__ __forceinline__ void cellp(char *smem, const float *gf, int tid,
                                             int l, const float *xbuf, float (&cst)[4]) {
    const int j  = tid % 80;
    const int r0 = (tid / 80) * 4;
    const float4 bb = ((const float4 *)(smem + SM_BIAS))[l * 80 + j];
    float4 wx = make_float4(0.f, 0.f, 0.f, 0.f);
    if (l == 0) wx = ((const float4 *)(smem + SM_W1X))[j];
    const int kk = (l == 0) ? j : (80 + j);
    __half *hb = (__half *)(smem + SM_B);
#pragma unroll
    for (int dr = 0; dr < 4; dr++) {
        const int r = r0 + dr;
        const float4 gv = *(const float4 *)(gf + r * GS + 4 * j);
        float iv = gv.x + bb.x, fv = gv.y + bb.y;
        float gg = gv.z + bb.z, ov = gv.w + bb.w;
        if (l == 0) {
            const float xr = xbuf[r];
            iv = fmaf(wx.x, xr, iv); fv = fmaf(wx.y, xr, fv);
            gg = fmaf(wx.z, xr, gg); ov = fmaf(wx.w, xr, ov);
        }
        const float cc = sigf(fv) * cst[dr] + sigf(iv) * tanhap(gg);
        cst[dr] = cc;
        hb[r * KB + kk] = __float2half_rn(sigf(ov) * tanhap(cc));
    }
}

static __device__ __forceinline__ void head_part(char *smem, int tid) {
    if (tid >= 128) return;
    const int q = tid >> 5, r = tid & 31;
    const __half *hb = (const __half *)(smem + SM_B);
    const float *wlin_s = (const float *)(smem + SM_WLIN);
    const __half2 *hv2 = (const __half2 *)(hb + r * KB + 80 + q * 20);
    float s = 0.0f;
#pragma unroll
    for (int jj = 0; jj < 10; jj++) {
        const __half2 hv = hv2[jj];
        s = fmaf(wlin_s[q * 20 + 2 * jj],     __half2float(__low2half(hv)),  s);
        s = fmaf(wlin_s[q * 20 + 2 * jj + 1], __half2float(__high2half(hv)), s);
    }
    ((float *)(smem + SM_PART))[q * 32 + r] = s;
}
static __device__ __forceinline__ void head_red(char *smem, int tid, float blin_v,
                                                float *out, int srow, int tOut) {
    if (tid >= NROW) return;
    const float *part = (const float *)(smem + SM_PART);
    out[srow * T + tOut] =
        blin_v + part[tid] + part[32 + tid] + part[64 + tid] + part[96 + tid];
}

// ---------------------------------------------------------------------------
__global__ void __launch_bounds__(NTHR, 1)
lstm_mma_kernel(const float *__restrict__ input,
                const float *__restrict__ w_ih1,
                const float *__restrict__ b_ih1, const float *__restrict__ b_hh1,
                const float *__restrict__ b_ih2, const float *__restrict__ b_hh2,
                const float *__restrict__ w_lin, const float *__restrict__ b_lin,
                float *__restrict__ out) {
    extern __shared__ char smem[];
    const int tid = threadIdx.x;
    const int wid = tid >> 5;
    const int lid = tid & 31;
    const int b0  = blockIdx.x * NROW;
    const uint32_t sb = smem_u32(smem);

    // B-fragment (weight) staging geometry: warp wid owns gr [16wid, 16wid+16)
    const uint32_t stBase = sb + SM_STAGE +
        (((uint32_t)wid * 16 + ((lid >> 4) & 1) * 8 + (lid & 7)) * KA1 +
         ((lid >> 3) & 1) * 8) * 2;
    // A-fragment (h) geometry: m16k16 tiles over h rows, stride KB
    const uint32_t aRow = (uint32_t)((lid & 7) + 8 * ((lid >> 3) & 1));
    const uint32_t aK8  = (uint32_t)(((lid >> 4) & 1) * 8);
    const uint32_t aB_h1 = sb + SM_B + (aRow * KB + aK8) * 2;    // h1: k 0..80
    const uint32_t aB_h2 = aB_h1 + 160;                           // h2: k 80..160

    // ---- init: scalars first (no overlap with staging window) ----
    {
        float *bias_s = (float *)(smem + SM_BIAS);
        float *w1x_s  = (float *)(smem + SM_W1X);
        for (int i = tid; i < 640; i += NTHR) {
            int l = i / 320, e = i % 320;
            int g = e & 3, j = e >> 2;
            int row = g * 80 + j;
            bias_s[i] = l ? (b_ih2[row] + b_hh2[row]) : (b_ih1[row] + b_hh1[row]);
        }
        for (int i = tid; i < 320; i += NTHR) {
            int g = i & 3, j = i >> 2;
            w1x_s[i] = w_ih1[g * 80 + j];
        }
        if (tid < H) ((float *)(smem + SM_WLIN))[tid] = w_lin[tid];
    }

    // ---- stage + hoist the 3 weight blocks into register B-fragments ----
    uint32_t bW1[5][2][2], bW2i[5][2][2], bW2o[5][2][2];
    {
        int4 *st = (int4 *)(smem + SM_STAGE);
        const int4 *s0 = (const int4 *)g_Wh;
        for (int i = tid; i < WBLK_BYTES / 16; i += NTHR) st[i] = s0[i];
        __syncthreads();
        hoistW(bW1, stBase);                                  // w_hh1
        __syncthreads();
        const int4 *s1 = (const int4 *)(g_Wh + 320 * KA1);
        for (int i = tid; i < WBLK_BYTES / 16; i += NTHR) st[i] = s1[i];
        __syncthreads();
        hoistW(bW2i, stBase);                                 // w_ih2
        __syncthreads();
        const int4 *s2 = (const int4 *)(g_Wh + 2 * 320 * KA1);
        for (int i = tid; i < WBLK_BYTES / 16; i += NTHR) st[i] = s2[i];
        __syncthreads();
        hoistW(bW2o, stBase);                                 // w_hh2
        __syncthreads();
    }

    // ---- zero h buffer and G1 (gates1(0)=0 since h1(-1)=0) ----
    {
        int4 z = make_int4(0, 0, 0, 0);
        int4 *dd = (int4 *)(smem + SM_B);
        for (int i = tid; i < B_BYTES / 16; i += NTHR) dd[i] = z;
        float *g1 = (float *)(smem + SM_G1);
        for (int i = tid; i < NROW * GS; i += NTHR) g1[i] = 0.0f;
    }

    float *gf1 = (float *)(smem + SM_G1);
    float *gf2 = (float *)(smem + SM_G2);
    float *xs  = (float *)(smem + SM_X);
    const float blin_v = b_lin[0];
    const int srow = b0 + (tid & 31);

    float c1[4], c2[4];
#pragma unroll
    for (int q = 0; q < 4; q++) { c1[q] = 0.0f; c2[q] = 0.0f; }

    if (tid < NROW) xs[tid] = input[srow * T + 0];
    __syncthreads();

    for (int t = 0; t < T; t++) {
        float xnext = 0.0f;
        if (tid < NROW && t + 1 < T) xnext = input[srow * T + (t + 1)];

        // ---- P1: gemm2-own(t) [W_hh2 @ h2(t-1)] (tensor) || cell1(t) (MUFU) ----
        float d2[2][2][4];
        dzero(d2);
        gemmS(bW2o, aB_h2, d2);                              // A = h2(t-1)
        cellp(smem, gf1, tid, 0, xs + (t & 1) * 32, c1);     // h1(t) -> B k=0..80
        __syncthreads();

        // ---- P2: gemm2-in(t) [W_ih2 @ h1(t)] || head_part(t-1) ----
        gemmS(bW2i, aB_h1, d2);                              // A = h1(t)
        epi(gf2, d2, wid, lid);
        if (t > 0) head_part(smem, tid);
        if (tid < NROW && t + 1 < T) xs[((t + 1) & 1) * 32 + tid] = xnext;
        __syncthreads();

        // ---- P3: cell2(t) (MUFU) || gemm1(t+1) [W_hh1 @ h1(t)] || head_red ----
        cellp(smem, gf2, tid, 1, nullptr, c2);               // h2(t) -> B k=80..160
        if (t + 1 < T) {
            float d1[2][2][4];
            dzero(d1);
            gemmS(bW1, aB_h1, d1);
            epi(gf1, d1, wid, lid);
        }
        if (t > 0) head_red(smem, tid, blin_v, out, srow, t - 1);
        __syncthreads();
    }

    // epilogue: head for t = T-1
    head_part(smem, tid);
    __syncthreads();
    head_red(smem, tid, blin_v, out, srow, T - 1);
}

extern "C" void kernel_launch(void *const *d_in, const int *in_sizes, int n_in,
                              void *d_out, int out_size) {
    const float *input = (const float *)d_in[0];
    const float *wih1  = (const float *)d_in[1];
    const float *whh1  = (const float *)d_in[2];
    const float *bih1  = (const float *)d_in[3];
    const float *bhh1  = (const float *)d_in[4];
    const float *wih2  = (const float *)d_in[5];
    const float *whh2  = (const float *)d_in[6];
    const float *bih2  = (const float *)d_in[7];
    const float *bhh2  = (const float *)d_in[8];
    const float *wlin  = (const float *)d_in[17];
    const float *blin  = (const float *)d_in[18];

    pack_w_kernel<<<(3 * 320 * KA1 + 255) / 256, 256>>>(whh1, wih2, whh2);

    cudaFuncSetAttribute(lstm_mma_kernel, cudaFuncAttributeMaxDynamicSharedMemorySize,
                         SMEM_TOTAL);
    lstm_mma_kernel<<<NCTA, NTHR, SMEM_TOTAL>>>(input, wih1, bih1, bhh1, bih2, bhh2,
                                                wlin, blin, (float *)d_out);
}